// round 14
// baseline (speedup 1.0000x reference)
#include <cuda_runtime.h>

#define NB 512
#define NT 1024
#define NK 48
#define SSTART 46
#define SEND 47
#define NEGV (-10000.0f)
#define L2E 1.4426950408889634f
#define LN2F 0.6931471805599453f

// per-batch slot: bp[NT*NK] u8 | v0[NK] | v1[NK] | e0[NK] | e1[NK] (each padded)
#define SLOT_V0 (NT*NK)
#define SLOT_V1 (SLOT_V0 + 256)
#define SLOT_E0 (SLOT_V1 + 256)
#define SLOT_E1 (SLOT_E0 + 256)
#define SLOT    (SLOT_E1 + 256)
#define TT_OFF  (4*SLOT)                     // masked trans table (shared by batches)
#define SMEM_BYTES (TT_OFF + NK*NK*4)        // ~209.9KB -> 1 CTA/SM

__device__ __forceinline__ float ex2f(float x){ float y; asm("ex2.approx.ftz.f32 %0, %1;":"=f"(y):"f"(x)); return y; }
__device__ __forceinline__ float lg2f(float x){ float y; asm("lg2.approx.f32 %0, %1;":"=f"(y):"f"(x)); return y; }
__device__ __forceinline__ unsigned long long ffma2(unsigned long long a, unsigned long long b, unsigned long long c){
    unsigned long long d; asm("fma.rn.f32x2 %0, %1, %2, %3;" : "=l"(d) : "l"(a), "l"(b), "l"(c)); return d;
}
__device__ __forceinline__ unsigned long long fadd2(unsigned long long a, unsigned long long b){
    unsigned long long d; asm("add.rn.f32x2 %0, %1, %2;" : "=l"(d) : "l"(a), "l"(b)); return d;
}
__device__ __forceinline__ unsigned long long pk2(float lo, float hi){
    unsigned long long d; asm("mov.b64 %0, {%1, %2};" : "=l"(d) : "f"(lo), "f"(hi)); return d;
}
__device__ __forceinline__ void upk2(unsigned long long v, float& lo, float& hi){
    asm("mov.b64 {%0, %1}, %2;" : "=f"(lo), "=f"(hi) : "l"(v));
}

// group maxima (independent) -> FMNMX tree for bm (short critical chain);
// index fully OFF the critical path: first group with mg==bm (SEL cascade,
// earliest-c order), then first-equal within group via bit-identical FADD
// recomputation from smem  => exact jnp.argmax first-max semantics.
#define VIT_STATE3(tp, jj, bm, bi) do { \
    float mg[12]; \
    _Pragma("unroll") \
    for (int c=0;c<12;++c){ \
        unsigned long long y01=fadd2(vv[c].x,(tp)[2*c]); \
        unsigned long long y23=fadd2(vv[c].y,(tp)[2*c+1]); \
        float y0,y1,y2,y3; upk2(y01,y0,y1); upk2(y23,y2,y3); \
        mg[c] = fmaxf(fmaxf(y0,y1), fmaxf(y2,y3)); \
    } \
    float u0=fmaxf(mg[0],mg[1]),  u1=fmaxf(mg[2],mg[3]),  u2=fmaxf(mg[4],mg[5]); \
    float u3=fmaxf(mg[6],mg[7]),  u4=fmaxf(mg[8],mg[9]),  u5=fmaxf(mg[10],mg[11]); \
    float w0=fmaxf(u0,u1), w1=fmaxf(u2,u3), w2=fmaxf(u4,u5); \
    bm = fmaxf(fmaxf(w0,w1), w2); \
    int g4 = (mg[0]==bm)?0:(mg[1]==bm)?1:(mg[2]==bm)?2:(mg[3]==bm)?3: \
             (mg[4]==bm)?4:(mg[5]==bm)?5:(mg[6]==bm)?6:(mg[7]==bm)?7: \
             (mg[8]==bm)?8:(mg[9]==bm)?9:(mg[10]==bm)?10:11; \
    const int p0 = 4*g4; \
    const float* trow = tT + (jj)*NK + p0; \
    float r0 = vcur[p0  ] + trow[0]; \
    float r1 = vcur[p0+1] + trow[1]; \
    float r2 = vcur[p0+2] + trow[2]; \
    bi = (r0==bm) ? p0 : (r1==bm) ? (p0+1) : (r2==bm) ? (p0+2) : (p0+3); \
} while(0)

__global__ __launch_bounds__(256, 1)
void crf_kernel(const float* __restrict__ feats,
                const float* __restrict__ trans,
                float* __restrict__ out)
{
    extern __shared__ char smc[];
    const int tid  = threadIdx.x;
    const int wid  = tid >> 5;
    const int lane = tid & 31;
    const int q    = wid & 3;                        // batch within CTA
    const bool isV = ((wid & 1) == (wid >> 2));      // SMSP gets 1 vit + 1 fwd
    const int b = blockIdx.x * 4 + q;
    char* sb = smc + q * SLOT;
    unsigned char* bp = (unsigned char*)sb;
    float* vS[2] = { (float*)(sb + SLOT_V0), (float*)(sb + SLOT_V1) };
    float* eS[2] = { (float*)(sb + SLOT_E0), (float*)(sb + SLOT_E1) };
    float* tT = (float*)(smc + TT_OFF);              // masked trans table (plain)
    const float* f = feats + (size_t)b * NT * NK;

    // cooperative fill of the masked trans table (one-time)
    for (int idx = tid; idx < NK*NK; idx += 256) {
        const int r = idx / NK, cpos = idx % NK;
        float tv = trans[idx];
        if (r == SSTART) tv = NEGV;                  // no transition into START row
        if (cpos == SEND) tv = NEGV;                 // no transition out of END col
        tT[idx] = tv;
    }

    const int  ll  = (lane < 24) ? lane : (lane - 24);
    const bool act = (lane < 24);
    const int  j1  = ll, j2 = ll + 24;               // two states per lane

    unsigned long long tpA[NK/2], tpB[NK/2];
    #pragma unroll
    for (int c = 0; c < NK/2; ++c) {
        const int p0 = 2*c, p1 = 2*c + 1;
        float a0 = trans[j1*NK+p0], a1 = trans[j1*NK+p1];
        float c0 = trans[j2*NK+p0], c1 = trans[j2*NK+p1];
        if (j1 == SSTART) { a0 = NEGV; a1 = NEGV; }
        if (j2 == SSTART) { c0 = NEGV; c1 = NEGV; }
        if (p0 == SEND)   { a0 = NEGV; c0 = NEGV; }
        if (p1 == SEND)   { a1 = NEGV; c1 = NEGV; }
        if (isV) { tpA[c] = pk2(a0, a1); tpB[c] = pk2(c0, c1); }     // plain (exact)
        else     { tpA[c] = pk2(ex2f(a0*L2E), ex2f(a1*L2E));          // exp-factored
                   tpB[c] = pk2(ex2f(c0*L2E), ex2f(c1*L2E)); }        // masked -> 0
    }
    if (act) {
        if (isV) { vS[0][j1] = (j1==SSTART)?0.f:NEGV;  vS[0][j2] = (j2==SSTART)?0.f:NEGV; }
        else     { eS[0][j1] = (j1==SSTART)?1.f:0.f;   eS[0][j2] = (j2==SSTART)?1.f:0.f; }
    }
    __syncthreads();                                  // table + init visible; then free-run

    float fq1[2], fq2[2];                            // 2-step feats prefetch
    fq1[0] = __ldg(f + j1);      fq2[0] = __ldg(f + j2);
    fq1[1] = __ldg(f + NK + j1); fq2[1] = __ldg(f + NK + j2);

    if (isV) {
        // ====== VITERBI: warp-private, double-buffered, short value chain ======
        #pragma unroll 1
        for (int g = 0; g < NT/2; ++g) {
            #pragma unroll
            for (int u = 0; u < 2; ++u) {            // read buf u, write buf u^1
                const int t = g*2 + u;
                const float* vcur = vS[u];
                ulonglong2 vv[12];
                const ulonglong2* vp = (const ulonglong2*)vcur;
                #pragma unroll
                for (int c = 0; c < 12; ++c) vv[c] = vp[c];        // broadcast LDS.128
                const float featv1 = fq1[u], featv2 = fq2[u];
                if (t + 2 < NT) { fq1[u] = __ldg(f + (t+2)*NK + j1);
                                  fq2[u] = __ldg(f + (t+2)*NK + j2); }
                float bm1, bm2; int bi1, bi2;
                VIT_STATE3(tpA, j1, bm1, bi1);       // exact max, first-max index
                VIT_STATE3(tpB, j2, bm2, bi2);
                if (act) {
                    vS[u^1][j1] = bm1 + featv1;      // emission added AFTER max (ref)
                    vS[u^1][j2] = bm2 + featv2;
                    *(unsigned short*)(bp + t*NK + 2*ll) =
                        (unsigned short)(bi1 | (bi2 << 8));
                }
                __syncwarp();
            }
        }
        if (lane == 0) {
            float bm = -3.4e38f; int last = 0;
            #pragma unroll
            for (int p = 0; p < NK; ++p) {
                float te = trans[SEND*NK + p];
                if (p == SEND) te = NEGV;
                float y = vS[0][p] + te;
                if (y > bm) { bm = y; last = p; }
            }
            out[NB + b] = bm;
            float* po = out + 2*NB + (size_t)b * NT;
            int tag = last;
            #pragma unroll 1
            for (int t = NT - 1; t >= 0; --t) {
                po[t] = (float)tag;
                int off = (tag < 24) ? (2*tag) : (2*tag - 47);
                tag = bp[t*NK + off];
            }
        }
    } else {
        // ====== FORWARD: warp-private; STALE shift (R5 recurrence) so the shfl
        //        is issued one step before it's consumed (off the chain) ======
        float Csum = 0.f, A1 = 0.f, A2 = 0.f, dNext = 0.f;
        #pragma unroll 1
        for (int g = 0; g < NT/2; ++g) {
            #pragma unroll
            for (int u = 0; u < 2; ++u) {
                const int t = g*2 + u;
                ulonglong2 vv[12];
                const ulonglong2* ep = (const ulonglong2*)eS[u];
                #pragma unroll
                for (int c = 0; c < 12; ++c) vv[c] = ep[c];        // broadcast LDS.128
                const float featv1 = fq1[u], featv2 = fq2[u];
                if (t + 2 < NT) { fq1[u] = __ldg(f + (t+2)*NK + j1);
                                  fq2[u] = __ldg(f + (t+2)*NK + j2); }
                unsigned long long a0=0ull, a1=0ull, a2=0ull, a3=0ull;
                #pragma unroll
                for (int c = 0; c < 12; ++c) {                     // packed f32x2 FFMA
                    a0 = ffma2(tpA[2*c  ], vv[c].x, a0);
                    a1 = ffma2(tpA[2*c+1], vv[c].y, a1);
                    a2 = ffma2(tpB[2*c  ], vv[c].x, a2);
                    a3 = ffma2(tpB[2*c+1], vv[c].y, a3);
                }
                float x0,x1,x2,x3,x4,x5,x6,x7;
                upk2(a0,x0,x1); upk2(a1,x2,x3); upk2(a2,x4,x5); upk2(a3,x6,x7);
                float s1 = (x0+x1)+(x2+x3);
                float s2 = (x4+x5)+(x6+x7);
                float raw1 = lg2f(s1) + featv1 * L2E;
                float raw2 = lg2f(s2) + featv2 * L2E;
                float d = fminf(fmaxf(dNext, -200.f), 200.f);  // stale A[0] (exact)
                Csum += d;
                A1 = raw1 - d; A2 = raw2 - d;
                dNext = __shfl_sync(0xffffffffu, A1, 0);       // consumed NEXT step
                if (act) { eS[u^1][j1] = ex2f(A1); eS[u^1][j2] = ex2f(A2); }
                __syncwarp();
            }
        }
        if (act) { eS[1][j1] = A1; eS[1][j2] = A2; }
        __syncwarp();
        if (lane == 0) {
            float m = -3.4e38f;
            #pragma unroll
            for (int p = 0; p < NK; ++p) {
                float te = trans[SEND*NK + p];
                if (p == SEND) te = NEGV;
                m = fmaxf(m, eS[1][p] + te * L2E);
            }
            float s = 0.f;
            #pragma unroll
            for (int p = 0; p < NK; ++p) {
                float te = trans[SEND*NK + p];
                if (p == SEND) te = NEGV;
                s += ex2f(eS[1][p] + te * L2E - m);
            }
            out[b] = (m + lg2f(s) + Csum) * LN2F;
        }
    }
}

extern "C" void kernel_launch(void* const* d_in, const int* in_sizes, int n_in,
                              void* d_out, int out_size)
{
    const float* feats = (const float*)d_in[0];
    const float* trans = (const float*)d_in[1];
    float* out = (float*)d_out;
    cudaFuncSetAttribute(crf_kernel, cudaFuncAttributeMaxDynamicSharedMemorySize,
                         SMEM_BYTES);
    cudaFuncSetAttribute(crf_kernel, cudaFuncAttributePreferredSharedMemoryCarveout,
                         100);
    crf_kernel<<<NB/4, 256, SMEM_BYTES>>>(feats, trans, out);
}